// round 15
// baseline (speedup 1.0000x reference)
#include <cuda_runtime.h>

// predictions [8,19,512,1024] f32, targets [8,512,1024] i32, output: scalar f32.
#define NB        8
#define NC        19
#define NPB       (512 * 1024)
#define LOG2_NPB  19
#define THRESH    0.7f
#define NMIN      10000

#define TPB       256
#define PIX_PER_T 4
#define NBLOCKS   ((NB * NPB) / (TPB * PIX_PER_T))   // 4096

__device__ double       g_sum[NB];
__device__ int          g_cnt[NB];
__device__ unsigned int g_done;

// CE loss recompute, exact f32 (rare exact-top-k fallback path only).
__device__ __forceinline__ float pixel_loss(const float* __restrict__ pred,
                                            const int*   __restrict__ tgt,
                                            int b, int i) {
    const int t = tgt[b * NPB + i];
    float s = 0.f, xt = 0.f;
#pragma unroll
    for (int c = 0; c < NC; c++) {
        const float v = pred[(b * NC + c) * NPB + i];
        s += __expf(v);
        if (c == t) xt = v;
    }
    float l = __logf(s) - xt;
    return l < 0.f ? 0.f : l;
}

__global__ void __launch_bounds__(TPB)
ohem_fused(const float* __restrict__ pred,
           const int*   __restrict__ tgt,
           float*       __restrict__ out) {
    // ---------------- phase 1: lean streaming CE ---------------------------
    const int tid4 = blockIdx.x * TPB + threadIdx.x;   // 4-pixel group id
    const int pix  = tid4 << 2;
    const int b    = pix >> LOG2_NPB;                  // uniform within a block
    const int n    = pix & (NPB - 1);

    const int4 t = __ldcg(reinterpret_cast<const int4*>(tgt + pix));

    const float4* p4       = reinterpret_cast<const float4*>(pred);
    const int     cstride4 = NPB / 4;
    const int     base4    = b * NC * cstride4 + (n >> 2);

    // Stream with __ldcg: cache at L2 (default policy), bypass L1.
    // R12(.cs)=6113 GB/s but gathers missed L2 (+142MB); R13(default)=L1
    // alloc throttled to 5529; R14(.cg stream, .nc gathers)=5631 with L1
    // at 26% from GATHER allocation. This round: .cg everywhere -> zero L1
    // allocation anywhere, L2-resident lines still serve the gathers.
    float4 s = make_float4(0.f, 0.f, 0.f, 0.f);
#pragma unroll
    for (int c = 0; c < NC; c++) {
        const float4 v = __ldcg(&p4[base4 + c * cstride4]);
        s.x += __expf(v.x);
        s.y += __expf(v.y);
        s.z += __expf(v.z);
        s.w += __expf(v.w);
    }

    // Target-logit gather AFTER the stream (lines L2-resident), no L1 alloc.
    const int base_e = b * (NC * NPB) + n;
    float4 l;
    l.x = __logf(s.x) - __ldcg(pred + base_e + t.x * NPB + 0);
    l.y = __logf(s.y) - __ldcg(pred + base_e + t.y * NPB + 1);
    l.z = __logf(s.z) - __ldcg(pred + base_e + t.z * NPB + 2);
    l.w = __logf(s.w) - __ldcg(pred + base_e + t.w * NPB + 3);

    float ls = 0.f;
    int   lc = 0;
    if (l.x > THRESH) { ls += l.x; lc++; }
    if (l.y > THRESH) { ls += l.y; lc++; }
    if (l.z > THRESH) { ls += l.z; lc++; }
    if (l.w > THRESH) { ls += l.w; lc++; }

#pragma unroll
    for (int o = 16; o; o >>= 1) {
        ls += __shfl_down_sync(0xffffffffu, ls, o);
        lc += __shfl_down_sync(0xffffffffu, lc, o);
    }

    __shared__ float        sh_f[TPB / 32];
    __shared__ int          sh_i[TPB / 32];
    __shared__ unsigned int sh_last;

    const int w = threadIdx.x >> 5, lane = threadIdx.x & 31;
    if (lane == 0) { sh_f[w] = ls; sh_i[w] = lc; }
    __syncthreads();

    if (threadIdx.x == 0) {
        double S = 0.0; int Cn = 0;
#pragma unroll
        for (int i = 0; i < TPB / 32; i++) { S += (double)sh_f[i]; Cn += sh_i[i]; }
        atomicAdd(&g_sum[b], S);
        atomicAdd(&g_cnt[b], Cn);
        __threadfence();
        const unsigned int tk = atomicAdd(&g_done, 1u);
        sh_last = (tk == (unsigned)(NBLOCKS - 1)) ? 1u : 0u;
    }
    __syncthreads();
    if (!sh_last) return;

    // ---------------- phase 2: finalize (last block only) ------------------
    __threadfence();

    __shared__ unsigned int hist[256];
    __shared__ unsigned int s_prefix;
    __shared__ int          s_k;
    __shared__ double       sh_d2[TPB / 32];
    __shared__ int          sh_i2[TPB / 32];
    __shared__ double       s_acc;

    if (threadIdx.x == 0) s_acc = 0.0;
    __syncthreads();

    for (int bb = 0; bb < NB; bb++) {
        const int    cnt = g_cnt[bb];
        const double sum = g_sum[bb];

        if (cnt >= NMIN) {
            if (threadIdx.x == 0) s_acc += sum / (double)cnt;
            __syncthreads();
        } else {
            // Exact top-NMIN via 4-pass MSB radix select (dead on this input).
            if (threadIdx.x == 0) { s_prefix = 0u; s_k = NMIN; }
            __syncthreads();
            for (int pass = 0; pass < 4; pass++) {
                const int shift = 24 - pass * 8;
                for (int i = threadIdx.x; i < 256; i += TPB) hist[i] = 0u;
                __syncthreads();
                const unsigned prefix  = s_prefix;
                const unsigned mask_hi = (pass == 0) ? 0u
                                       : (0xFFFFFFFFu << (shift + 8));
                for (int i = threadIdx.x; i < NPB; i += TPB) {
                    const unsigned u = __float_as_uint(pixel_loss(pred, tgt, bb, i));
                    if ((u & mask_hi) == prefix)
                        atomicAdd(&hist[(u >> shift) & 255u], 1u);
                }
                __syncthreads();
                if (threadIdx.x == 0) {
                    int kk = s_k;
                    int d  = 255;
                    while (d > 0 && (int)hist[d] < kk) { kk -= (int)hist[d]; d--; }
                    s_prefix = prefix | ((unsigned)d << shift);
                    s_k      = kk;
                }
                __syncthreads();
            }
            const float pivot = __uint_as_float(s_prefix);
            double fs = 0.0; int fg = 0;
            for (int i = threadIdx.x; i < NPB; i += TPB) {
                const float vv = pixel_loss(pred, tgt, bb, i);
                if (vv > pivot) { fs += (double)vv; fg++; }
            }
#pragma unroll
            for (int o = 16; o; o >>= 1) {
                fs += __shfl_down_sync(0xffffffffu, fs, o);
                fg += __shfl_down_sync(0xffffffffu, fg, o);
            }
            if (lane == 0) { sh_d2[w] = fs; sh_i2[w] = fg; }
            __syncthreads();
            if (threadIdx.x == 0) {
                double S = 0.0; int G = 0;
#pragma unroll
                for (int i = 0; i < TPB / 32; i++) { S += sh_d2[i]; G += sh_i2[i]; }
                const double kept = S + (double)(NMIN - G) * (double)pivot;
                s_acc += kept / (double)NMIN;
            }
            __syncthreads();
        }
    }

    if (threadIdx.x == 0) {
        out[0] = (float)(s_acc / (double)NB);
#pragma unroll
        for (int i = 0; i < NB; i++) { g_sum[i] = 0.0; g_cnt[i] = 0; }
        g_done = 0u;
        __threadfence();
    }
}

extern "C" void kernel_launch(void* const* d_in, const int* in_sizes, int n_in,
                              void* d_out, int out_size) {
    const float* pred = (const float*)d_in[0];
    const int*   tgt  = (const int*)d_in[1];
    float*       out  = (float*)d_out;

    ohem_fused<<<NBLOCKS, TPB>>>(pred, tgt, out);
}